// round 1
// baseline (speedup 1.0000x reference)
#include <cuda_runtime.h>

// Problem dims (fixed by the dataset)
#define DD 1024
#define MM 512
#define CC 256
#define BB 8192

#define NEWTON_ITERS 16

// ---------------- scratch (device globals: allocation-free) ----------------
__device__ float g_state_p[(size_t)DD * BB];   // 32 MB
__device__ float g_T1[DD * DD];                // F @ Sigma
__device__ float g_cov_p[DD * DD];
__device__ float g_HP[MM * DD];                // H @ cov_p
__device__ float g_S[MM * MM];                 // innovation covariance
__device__ float g_PHt[DD * MM];               // cov_p @ H^T
__device__ float g_Xa[MM * MM];                // Newton ping
__device__ float g_Xb[MM * MM];                // Newton pong
__device__ float g_Tm[MM * MM];                // S @ X
__device__ float g_K[DD * MM];                 // Kalman gain
__device__ float g_innov[(size_t)MM * BB];     // 16 MB

__device__ unsigned g_n1_bits;
__device__ unsigned g_ninf_bits;
__device__ float    g_scale;

// ---------------- generic tiled SGEMM ----------------
// C[M,N] = alpha * (A[M,K] @ op(B)) + beta * E[M,N]
// op(B) = B[K,N] (TB=false) or B[N,K]^T (TB=true). All row-major.
// E may be nullptr (beta ignored) and may alias C (thread-private elements).
template <int BM, int BN, int BK, int TM, int TN, bool TB>
__global__ void __launch_bounds__((BM / TM) * (BN / TN))
gemm_k(const float* __restrict__ A, const float* __restrict__ B,
       const float* E, float* C,
       int M, int N, int K, float alpha, float beta)
{
    constexpr int THREADS = (BM / TM) * (BN / TN);
    constexpr int A_LD = (BM * BK) / (THREADS * 4);   // float4 loads per thread
    constexpr int B_LD = (BN * BK) / (THREADS * 4);
    static_assert(A_LD >= 1 && B_LD >= 1, "tile too small");

    __shared__ float As[BK][BM];
    __shared__ float Bs[BK][BN];

    const int tid = threadIdx.x;
    const int bm = blockIdx.y * BM;
    const int bn = blockIdx.x * BN;
    constexpr int TCOLS = BN / TN;
    const int tx = tid % TCOLS;
    const int ty = tid / TCOLS;

    float acc[TM][TN];
#pragma unroll
    for (int i = 0; i < TM; ++i)
#pragma unroll
        for (int j = 0; j < TN; ++j) acc[i][j] = 0.0f;

    for (int k0 = 0; k0 < K; k0 += BK) {
        // ---- load A tile (transposed into smem: As[k][m]) ----
#pragma unroll
        for (int li = 0; li < A_LD; ++li) {
            int idx = tid + li * THREADS;           // float4 index over BM x (BK/4)
            int row = idx / (BK / 4);
            int kc = (idx % (BK / 4)) * 4;
            float4 v = *reinterpret_cast<const float4*>(
                &A[(size_t)(bm + row) * K + k0 + kc]);
            As[kc + 0][row] = v.x;
            As[kc + 1][row] = v.y;
            As[kc + 2][row] = v.z;
            As[kc + 3][row] = v.w;
        }
        // ---- load B tile ----
        if constexpr (!TB) {
#pragma unroll
            for (int li = 0; li < B_LD; ++li) {
                int idx = tid + li * THREADS;       // float4 index over BK x (BN/4)
                int kr = idx / (BN / 4);
                int nc = (idx % (BN / 4)) * 4;
                float4 v = *reinterpret_cast<const float4*>(
                    &B[(size_t)(k0 + kr) * N + bn + nc]);
                *reinterpret_cast<float4*>(&Bs[kr][nc]) = v;
            }
        } else {
#pragma unroll
            for (int li = 0; li < B_LD; ++li) {
                int idx = tid + li * THREADS;       // float4 index over BN x (BK/4)
                int nrow = idx / (BK / 4);
                int kc = (idx % (BK / 4)) * 4;
                float4 v = *reinterpret_cast<const float4*>(
                    &B[(size_t)(bn + nrow) * K + k0 + kc]);
                Bs[kc + 0][nrow] = v.x;
                Bs[kc + 1][nrow] = v.y;
                Bs[kc + 2][nrow] = v.z;
                Bs[kc + 3][nrow] = v.w;
            }
        }
        __syncthreads();

        // ---- compute ----
#pragma unroll
        for (int kk = 0; kk < BK; ++kk) {
            float ra[TM], rb[TN];
#pragma unroll
            for (int i = 0; i < TM; i += 4)
                *reinterpret_cast<float4*>(&ra[i]) =
                    *reinterpret_cast<const float4*>(&As[kk][ty * TM + i]);
#pragma unroll
            for (int j = 0; j < TN; j += 4)
                *reinterpret_cast<float4*>(&rb[j]) =
                    *reinterpret_cast<const float4*>(&Bs[kk][tx * TN + j]);
#pragma unroll
            for (int i = 0; i < TM; ++i)
#pragma unroll
                for (int j = 0; j < TN; ++j)
                    acc[i][j] += ra[i] * rb[j];
        }
        __syncthreads();
    }

    // ---- epilogue ----
#pragma unroll
    for (int i = 0; i < TM; ++i) {
        int row = bm + ty * TM + i;
#pragma unroll
        for (int j = 0; j < TN; j += 4) {
            int col = bn + tx * TN + j;
            float4 r;
            r.x = alpha * acc[i][j + 0];
            r.y = alpha * acc[i][j + 1];
            r.z = alpha * acc[i][j + 2];
            r.w = alpha * acc[i][j + 3];
            if (E != nullptr) {
                float4 e = *reinterpret_cast<const float4*>(
                    &E[(size_t)row * N + col]);
                r.x += beta * e.x;
                r.y += beta * e.y;
                r.z += beta * e.z;
                r.w += beta * e.w;
            }
            *reinterpret_cast<float4*>(&C[(size_t)row * N + col]) = r;
        }
    }
}

// ---------------- norm + init kernels for Newton-Schulz ----------------
__global__ void reset_norms_k()
{
    g_n1_bits = 0u;
    g_ninf_bits = 0u;
}

__global__ void rowsum_k(const float* __restrict__ S, int n)
{
    __shared__ float sh[256];
    int r = blockIdx.x;
    float s = 0.0f;
    for (int c = threadIdx.x; c < n; c += 256) s += fabsf(S[(size_t)r * n + c]);
    sh[threadIdx.x] = s;
    __syncthreads();
    for (int o = 128; o > 0; o >>= 1) {
        if (threadIdx.x < o) sh[threadIdx.x] += sh[threadIdx.x + o];
        __syncthreads();
    }
    if (threadIdx.x == 0) atomicMax(&g_ninf_bits, __float_as_uint(sh[0]));
}

__global__ void colsum_k(const float* __restrict__ S, int n)
{
    __shared__ float sh[256];
    int c = blockIdx.x;
    float s = 0.0f;
    for (int r = threadIdx.x; r < n; r += 256) s += fabsf(S[(size_t)r * n + c]);
    sh[threadIdx.x] = s;
    __syncthreads();
    for (int o = 128; o > 0; o >>= 1) {
        if (threadIdx.x < o) sh[threadIdx.x] += sh[threadIdx.x + o];
        __syncthreads();
    }
    if (threadIdx.x == 0) atomicMax(&g_n1_bits, __float_as_uint(sh[0]));
}

__global__ void scale_k()
{
    g_scale = 1.0f / (__uint_as_float(g_n1_bits) * __uint_as_float(g_ninf_bits));
}

// X0 = S^T * scale
__global__ void init_x0_k(const float* __restrict__ S, float* __restrict__ X, int n)
{
    int idx = blockIdx.x * blockDim.x + threadIdx.x;
    if (idx < n * n) {
        int i = idx / n;
        int j = idx % n;
        X[idx] = S[(size_t)j * n + i] * g_scale;
    }
}

// ---------------- host-side launch helpers ----------------
template <bool TB>
static void gemm_big(const float* A, const float* B, const float* E, float* C,
                     int M, int N, int K, float alpha, float beta)
{
    dim3 grid(N / 128, M / 128);
    gemm_k<128, 128, 8, 8, 8, TB><<<grid, 256>>>(A, B, E, C, M, N, K, alpha, beta);
}

template <bool TB>
static void gemm_mid(const float* A, const float* B, const float* E, float* C,
                     int M, int N, int K, float alpha, float beta)
{
    dim3 grid(N / 64, M / 64);
    gemm_k<64, 64, 16, 4, 4, TB><<<grid, 256>>>(A, B, E, C, M, N, K, alpha, beta);
}

extern "C" void kernel_launch(void* const* d_in, const int* in_sizes, int n_in,
                              void* d_out, int out_size)
{
    (void)in_sizes; (void)n_in; (void)out_size;

    const float* state     = (const float*)d_in[0];  // [D, B]
    const float* state_cov = (const float*)d_in[1];  // [D, D]
    const float* meas      = (const float*)d_in[2];  // [M, B]
    const float* control   = (const float*)d_in[3];  // [C, B]
    const float* F         = (const float*)d_in[4];  // [D, D]
    const float* Q         = (const float*)d_in[5];  // [D, D]
    const float* Bc        = (const float*)d_in[6];  // [D, C]
    const float* H         = (const float*)d_in[7];  // [M, D]
    const float* R         = (const float*)d_in[8];  // [M, M]

    float *state_p, *T1, *cov_p, *HP, *S, *PHt, *Xa, *Xb, *Tm, *Kg, *innov;
    cudaGetSymbolAddress((void**)&state_p, g_state_p);
    cudaGetSymbolAddress((void**)&T1, g_T1);
    cudaGetSymbolAddress((void**)&cov_p, g_cov_p);
    cudaGetSymbolAddress((void**)&HP, g_HP);
    cudaGetSymbolAddress((void**)&S, g_S);
    cudaGetSymbolAddress((void**)&PHt, g_PHt);
    cudaGetSymbolAddress((void**)&Xa, g_Xa);
    cudaGetSymbolAddress((void**)&Xb, g_Xb);
    cudaGetSymbolAddress((void**)&Tm, g_Tm);
    cudaGetSymbolAddress((void**)&Kg, g_K);
    cudaGetSymbolAddress((void**)&innov, g_innov);

    float* out_state = (float*)d_out;                    // [D, B]
    float* out_cov   = out_state + (size_t)DD * BB;      // [D, D]

    // ---- prediction ----
    // state_p = F @ state + Bc @ control
    gemm_big<false>(F, state, nullptr, state_p, DD, BB, DD, 1.0f, 0.0f);
    gemm_big<false>(Bc, control, state_p, state_p, DD, BB, CC, 1.0f, 1.0f);

    // cov_p = F @ state_cov @ F^T + Q
    gemm_mid<false>(F, state_cov, nullptr, T1, DD, DD, DD, 1.0f, 0.0f);
    gemm_mid<true >(T1, F, Q, cov_p, DD, DD, DD, 1.0f, 1.0f);

    // ---- correction prep ----
    gemm_mid<false>(H, cov_p, nullptr, HP, MM, DD, DD, 1.0f, 0.0f);   // HP = H @ cov_p
    gemm_mid<true >(HP, H, R, S, MM, MM, DD, 1.0f, 1.0f);             // S  = HP @ H^T + R
    gemm_mid<true >(cov_p, H, nullptr, PHt, DD, MM, DD, 1.0f, 0.0f);  // PHt = cov_p @ H^T

    // ---- S^-1 via Newton-Schulz: X0 = S^T/(|S|_1 |S|_inf), X <- X(2I - S X) ----
    reset_norms_k<<<1, 1>>>();
    rowsum_k<<<MM, 256>>>(S, MM);
    colsum_k<<<MM, 256>>>(S, MM);
    scale_k<<<1, 1>>>();
    init_x0_k<<<(MM * MM + 255) / 256, 256>>>(S, Xa, MM);

    float* X = Xa;
    float* Xn = Xb;
    for (int it = 0; it < NEWTON_ITERS; ++it) {
        gemm_mid<false>(S, X, nullptr, Tm, MM, MM, MM, 1.0f, 0.0f);   // T = S @ X
        gemm_mid<false>(X, Tm, X, Xn, MM, MM, MM, -1.0f, 2.0f);       // Xn = 2X - X@T
        float* t = X; X = Xn; Xn = t;
    }

    // ---- gain + correction ----
    gemm_mid<false>(PHt, X, nullptr, Kg, DD, MM, MM, 1.0f, 0.0f);     // K = PHt @ S^-1
    gemm_big<false>(H, state_p, meas, innov, MM, BB, DD, -1.0f, 1.0f);// innov = meas - H@state_p
    gemm_big<false>(Kg, innov, state_p, out_state, DD, BB, MM, 1.0f, 1.0f); // state_n
    gemm_mid<false>(Kg, HP, cov_p, out_cov, DD, DD, MM, -1.0f, 1.0f); // cov_n = cov_p - K@HP
}